// round 17
// baseline (speedup 1.0000x reference)
#include <cuda_runtime.h>

// Problem constants: N=1, C=4, D=3, H=W=64
#define NELEM 49152      // 4*3*64*64
#define HW    4096
#define PERCH 12288      // D*H*W per channel
#define XPAD  87120      // 4 * 5 * 66 * 66

__device__ float  d_xpad[XPAD];        // zero-padded x: [c][zd+1][h+1][w+1]
__device__ float  d_vpre[NELEM];
__device__ float  d_kqpre[NELEM];
__device__ float  d_part[16 * 48];     // [quant(4)*chan(4)][48 block partials]
__device__ float  d_v[NELEM];
__device__ float  d_q[NELEM];

// sparsity-compacted state (per slice of 4096)
__device__ int    d_nnz[12];
__device__ int    d_P[12];             // nnz padded up to multiple of 128
__device__ float  d_qnz[NELEM];        // compacted q values (padding = 0)
__device__ int    d_idxnz[NELEM];      // compacted k -> original pos
__device__ int    d_rank[NELEM];       // original pos -> compacted k (nz only)
__device__ float  d_S0[12];            // sum_{zero i} v_i / 4096
__device__ float  d_AnzP[12][16];      // per-chunk Anz partials
__device__ float2 d_qanz[NELEM];       // compacted {qln_i, a_i} (padding = {0,0})
__device__ float  d_ppart[16 * NELEM]; // pass2 chunk partials (compacted idx)

__device__ __forceinline__ float ex2f_(float x) {
    float y;
    asm("ex2.approx.f32 %0, %1;" : "=f"(y) : "f"(x));
    return y;
}

#define L2E 1.4426950408889634f

// ---------------------------------------------------------------------------
// K0: zero-pad x into d_xpad. grid 341 x 256
// ---------------------------------------------------------------------------
__global__ void k_pad(const float* __restrict__ x)
{
    int i = blockIdx.x * 256 + threadIdx.x;
    if (i >= XPAD) return;
    int c  = i / 21780;
    int r0 = i % 21780;
    int p  = r0 / 4356;
    int r1 = r0 % 4356;
    int row = r1 / 66;
    int col = r1 % 66;
    float val = 0.f;
    if (p >= 1 && p <= 3 && row >= 1 && row <= 64 && col >= 1 && col <= 64)
        val = x[c * PERCH + (p - 1) * 4096 + ((row - 1) << 6) + (col - 1)];
    d_xpad[i] = val;
}

// ---------------------------------------------------------------------------
// K1: branchless conv3 (padded) + conv1 + bias; per-block stats partials
// ---------------------------------------------------------------------------
__global__ void k_conv(const float* __restrict__ x, const float* __restrict__ W3,
                       const float* __restrict__ b3, const float* __restrict__ W1,
                       const float* __restrict__ b1)
{
    __shared__ float sW3[432], sW1[16], sb3[4], sb1[4];
    int t = threadIdx.x;
    for (int i = t; i < 432; i += 256) sW3[i] = W3[i];
    if (t < 16)  sW1[t] = W1[t];
    if (t < 4) { sb3[t] = b3[t]; sb1[t] = b1[t]; }
    __syncthreads();

    int idx = blockIdx.x * 256 + t;
    int o  = idx / PERCH;
    int r  = idx % PERCH;
    int d  = r >> 12;
    int hw = r & 4095;
    int h  = hw >> 6;
    int w  = hw & 63;

    float acc3 = sb3[o], acc1 = sb1[o];
    int poff = h * 66 + w;                 // (h+kh)(w+kw) base at kh=kw=0
    #pragma unroll
    for (int i = 0; i < 4; i++) {
        acc1 = fmaf(x[i * PERCH + (d << 12) + hw], sW1[o * 4 + i], acc1);
        const float* xp = d_xpad + (i * 5 + d) * 4356 + poff;
        const float* wk = sW3 + (o * 4 + i) * 27;
        #pragma unroll
        for (int kd = 0; kd < 3; kd++)
            #pragma unroll
            for (int kh = 0; kh < 3; kh++)
                #pragma unroll
                for (int kw = 0; kw < 3; kw++)
                    acc3 = fmaf(xp[kd * 4356 + kh * 66 + kw],
                                wk[kd * 9 + kh * 3 + kw], acc3);
    }
    d_vpre[idx]  = acc3;
    d_kqpre[idx] = acc1;

    float v0 = acc3, v1 = acc3 * acc3, v2 = acc1, v3 = acc1 * acc1;
    #pragma unroll
    for (int off = 16; off; off >>= 1) {
        v0 += __shfl_down_sync(0xffffffffu, v0, off);
        v1 += __shfl_down_sync(0xffffffffu, v1, off);
        v2 += __shfl_down_sync(0xffffffffu, v2, off);
        v3 += __shfl_down_sync(0xffffffffu, v3, off);
    }
    __shared__ float sred[8][4];
    int wid = t >> 5, lane = t & 31;
    if (lane == 0) { sred[wid][0] = v0; sred[wid][1] = v1; sred[wid][2] = v2; sred[wid][3] = v3; }
    __syncthreads();
    if (t == 0) {
        float s0 = 0, s1 = 0, s2 = 0, s3 = 0;
        #pragma unroll
        for (int i = 0; i < 8; i++) { s0 += sred[i][0]; s1 += sred[i][1]; s2 += sred[i][2]; s3 += sred[i][3]; }
        int b2 = blockIdx.x % 48;
        d_part[(0 * 4 + o) * 48 + b2] = s0;
        d_part[(1 * 4 + o) * 48 + b2] = s1;
        d_part[(2 * 4 + o) * 48 + b2] = s2;
        d_part[(3 * 4 + o) * 48 + b2] = s3;
    }
}

// ---------------------------------------------------------------------------
// K2: fused stats + BN/ReLU + compaction. grid 12 x 1024 (block=slice)
// ---------------------------------------------------------------------------
__global__ void k_prep(const float* __restrict__ g3, const float* __restrict__ be3,
                       const float* __restrict__ g1, const float* __restrict__ be1)
{
    __shared__ float scoef[4];
    __shared__ float ssum[4];
    __shared__ int   soff[32];
    __shared__ float sv[32];
    __shared__ int   s_nnz, s_P;

    int s = blockIdx.x, t = threadIdx.x;
    int lane = t & 31, w = t >> 5;
    int c = s / 3;                        // channel
    int sb = s * 4096;
    int pos = t * 4;

    float4 pre3 = *(const float4*)(d_vpre  + sb + pos);
    float4 pre1 = *(const float4*)(d_kqpre + sb + pos);

    if (s == 0 && t < 192) ((float*)d_AnzP)[t] = 0.f;

    if (t < 4) {
        const float* p = d_part + (t * 4 + c) * 48;
        float a = 0.f;
        #pragma unroll
        for (int i = 0; i < 48; i++) a += p[i];
        ssum[t] = a;
    }
    __syncthreads();
    if (t == 0) {
        const float inv_n = 1.0f / 12288.0f;
        float m3  = ssum[0] * inv_n;
        float vr3 = ssum[1] * inv_n - m3 * m3;
        float sc3 = g3[c] * rsqrtf(vr3 + 1e-5f);
        float m1  = ssum[2] * inv_n;
        float vr1 = ssum[3] * inv_n - m1 * m1;
        float sc1 = g1[c] * rsqrtf(vr1 + 1e-5f);
        scoef[0] = sc3; scoef[1] = be3[c] - m3 * sc3;
        scoef[2] = sc1; scoef[3] = be1[c] - m1 * sc1;
    }
    __syncthreads();
    float sc3 = scoef[0], sh3 = scoef[1], sc1 = scoef[2], sh1 = scoef[3];

    float4 vv, qv;
    vv.x = fmaxf(fmaf(pre3.x, sc3, sh3), 0.f);
    vv.y = fmaxf(fmaf(pre3.y, sc3, sh3), 0.f);
    vv.z = fmaxf(fmaf(pre3.z, sc3, sh3), 0.f);
    vv.w = fmaxf(fmaf(pre3.w, sc3, sh3), 0.f);
    qv.x = fmaxf(fmaf(pre1.x, sc1, sh1), 0.f);
    qv.y = fmaxf(fmaf(pre1.y, sc1, sh1), 0.f);
    qv.z = fmaxf(fmaf(pre1.z, sc1, sh1), 0.f);
    qv.w = fmaxf(fmaf(pre1.w, sc1, sh1), 0.f);
    *(float4*)(d_v + sb + pos) = vv;
    *(float4*)(d_q + sb + pos) = qv;

    int c0 = qv.x > 0.f, c1 = qv.y > 0.f, c2 = qv.z > 0.f, c3 = qv.w > 0.f;
    int cnt = c0 + c1 + c2 + c3;
    float vz = (c0 ? 0.f : vv.x) + (c1 ? 0.f : vv.y)
             + (c2 ? 0.f : vv.z) + (c3 ? 0.f : vv.w);

    int inc = cnt;                        // warp inclusive scan
    #pragma unroll
    for (int off = 1; off < 32; off <<= 1) {
        int n = __shfl_up_sync(0xffffffffu, inc, off);
        if (lane >= off) inc += n;
    }
    float vzr = vz;
    #pragma unroll
    for (int off = 16; off; off >>= 1) vzr += __shfl_down_sync(0xffffffffu, vzr, off);
    if (lane == 31) soff[w] = inc;
    if (lane == 0)  sv[w]   = vzr;
    __syncthreads();
    if (t == 0) {
        int acc = 0; float vacc = 0.f;
        #pragma unroll
        for (int i = 0; i < 32; i++) {
            int tmp = soff[i]; soff[i] = acc; acc += tmp;
            vacc += sv[i];
        }
        s_nnz = acc;
        s_P   = (acc + 127) & ~127;
        d_nnz[s]  = acc;
        d_P[s]    = s_P;
        d_S0[s]   = vacc * (1.0f / 4096.0f);
    }
    __syncthreads();
    int k = soff[w] + (inc - cnt);
    if (c0) { d_qnz[sb + k] = qv.x; d_idxnz[sb + k] = pos;     d_rank[sb + pos]     = k; k++; }
    if (c1) { d_qnz[sb + k] = qv.y; d_idxnz[sb + k] = pos + 1; d_rank[sb + pos + 1] = k; k++; }
    if (c2) { d_qnz[sb + k] = qv.z; d_idxnz[sb + k] = pos + 2; d_rank[sb + pos + 2] = k; k++; }
    if (c3) { d_qnz[sb + k] = qv.w; d_idxnz[sb + k] = pos + 3; d_rank[sb + pos + 3] = k; k++; }
    for (int i = s_nnz + t; i < s_P; i += 1024) {
        d_qnz[sb + i]  = 0.f;
        d_qanz[sb + i] = make_float2(0.f, 0.f);
    }
}

// ---------------------------------------------------------------------------
// K3: pass1 (R11/R15 proven config): 1 row/lane, 32 rows/block, 8 warp-chunks.
// grid 1536 x 256: slice = blk>>7, rowgroup(32) = blk&127, chunk = warp
// ---------------------------------------------------------------------------
__global__ void k_pass1()
{
    int s = blockIdx.x >> 7;
    int g = blockIdx.x & 127;
    int nnz = d_nnz[s];
    if (g * 32 >= nnz) return;
    __shared__ float sq[4096];
    __shared__ float partZ[8][32];
    int t = threadIdx.x, w = t >> 5, lane = t & 31;
    int sb = s << 12;
    int P  = d_P[s];
    int P4 = P >> 2;

    float4* sq4 = (float4*)sq;
    const float4* gq4 = (const float4*)(d_qnz + sb);
    for (int j = t; j < P4; j += 256) sq4[j] = gq4[j];
    __syncthreads();

    int k = g * 32 + lane;
    float qi   = (k < P) ? sq[k] : 0.f;
    float qln  = qi * L2E;

    int P32 = P >> 5;                      // float4s per warp chunk (mult of 4)
    const float4* p = (const float4*)sq + w * P32;
    float z0 = 0, z1 = 0, z2 = 0, z3 = 0;
    float z4 = 0, z5 = 0, z6 = 0, z7 = 0;
    for (int it = P32 >> 1; it > 0; it--, p += 2) {
        float4 qa = p[0];
        float4 qb = p[1];
        z0 += ex2f_(qln * qa.x);
        z1 += ex2f_(qln * qa.y);
        z2 += ex2f_(qln * qa.z);
        z3 += ex2f_(qln * qa.w);
        z4 += ex2f_(qln * qb.x);
        z5 += ex2f_(qln * qb.y);
        z6 += ex2f_(qln * qb.z);
        z7 += ex2f_(qln * qb.w);
    }
    partZ[w][lane] = ((z0 + z1) + (z2 + z3)) + ((z4 + z5) + (z6 + z7));
    __syncthreads();
    if (w == 0 && k < nnz) {
        // unshifted: q>=0, exponents bounded (~2^30 max) — fp32-safe.
        float Z = (((partZ[0][lane] + partZ[1][lane]) + (partZ[2][lane] + partZ[3][lane]))
                +  ((partZ[4][lane] + partZ[5][lane]) + (partZ[6][lane] + partZ[7][lane])))
                + (float)(4096 - P);
        int row = d_idxnz[sb + k];
        float av = d_v[sb + row] / Z;
        d_qanz[sb + k] = make_float2(qln, av);
    }
}

// ---------------------------------------------------------------------------
// K4: pass2, 16 i-chunks, 256 thr (256 rows/block share one chunk load).
// grid 3072 x 256: slice = blk>>8; chunk = (blk&255)&15; rowgroup(256) = (blk&255)>>4
// ---------------------------------------------------------------------------
__global__ void k_pass2()
{
    int s   = blockIdx.x >> 8;
    int rem = blockIdx.x & 255;
    int c   = rem & 15;
    int g   = rem >> 4;                    // [0,16)
    int nnz = d_nnz[s];
    if (g * 256 >= nnz) return;
    int P   = d_P[s];
    int P16 = P >> 4;                      // entries per chunk (mult of 8)
    __shared__ float2 sqa[256];            // up to 2 KB
    __shared__ float sanz[8];
    int t = threadIdx.x;
    int sb = s << 12;

    float4* s4 = (float4*)sqa;
    const float4* g4 = (const float4*)(d_qanz + sb + c * P16);
    int nf4 = P16 >> 1;                    // float4s in chunk (mult of 4)
    for (int j = t; j < nf4; j += 256) s4[j] = g4[j];
    __syncthreads();

    // Anz chunk partial (only g==0 blocks; data already in smem)
    if (g == 0) {
        int w = t >> 5, lane = t & 31;
        float a = 0.f;
        for (int i = t; i < P16; i += 256) a += sqa[i].y;
        #pragma unroll
        for (int off = 16; off; off >>= 1) a += __shfl_down_sync(0xffffffffu, a, off);
        if (lane == 0) sanz[w] = a;
    }

    int k = g * 256 + t;
    float qj = d_qnz[sb + ((k < nnz) ? k : 0)];
    float a0 = 0, a1 = 0, a2 = 0, a3 = 0;
    float a4 = 0, a5 = 0, a6 = 0, a7 = 0;
    const float4* p = (const float4*)sqa;
    for (int it = nf4 >> 2; it > 0; it--, p += 4) {
        float4 u0 = p[0];
        float4 u1 = p[1];
        float4 u2 = p[2];
        float4 u3 = p[3];
        a0 = fmaf(u0.y, ex2f_(u0.x * qj), a0);
        a1 = fmaf(u0.w, ex2f_(u0.z * qj), a1);
        a2 = fmaf(u1.y, ex2f_(u1.x * qj), a2);
        a3 = fmaf(u1.w, ex2f_(u1.z * qj), a3);
        a4 = fmaf(u2.y, ex2f_(u2.x * qj), a4);
        a5 = fmaf(u2.w, ex2f_(u2.z * qj), a5);
        a6 = fmaf(u3.y, ex2f_(u3.x * qj), a6);
        a7 = fmaf(u3.w, ex2f_(u3.z * qj), a7);
    }
    if (k < nnz)
        d_ppart[c * NELEM + sb + k] = ((a0 + a1) + (a2 + a3)) + ((a4 + a5) + (a6 + a7));

    if (g == 0) {
        __syncthreads();
        if (t == 0)
            d_AnzP[s][c] = ((sanz[0] + sanz[1]) + (sanz[2] + sanz[3]))
                         + ((sanz[4] + sanz[5]) + (sanz[6] + sanz[7]));
    }
}

// ---------------------------------------------------------------------------
// K5: final — Datt inline + assemble Patt + residual. grid 64 x 256 over (c,hw)
// ---------------------------------------------------------------------------
__global__ void k_final(const float* __restrict__ x, const float* __restrict__ gama,
                        float* __restrict__ out)
{
    int tid = blockIdx.x * 256 + threadIdx.x;   // 0..16383
    int c = tid >> 12, hw = tid & 4095;
    int base = c * PERCH + hw;
    float gm = gama[0];

    float q0 = d_q[base], q1 = d_q[base + HW], q2 = d_q[base + 2 * HW];
    float v0 = d_v[base], v1 = d_v[base + HW], v2 = d_v[base + 2 * HW];

    float qm = fmaxf(q0, fmaxf(q1, q2));
    float o0 = 0, o1 = 0, o2 = 0;
    {
        float ql = q0 * L2E, nm = -ql * qm;
        float e0 = ex2f_(fmaf(ql, q0, nm)), e1 = ex2f_(fmaf(ql, q1, nm)), e2 = ex2f_(fmaf(ql, q2, nm));
        float w_ = v0 / (e0 + e1 + e2);
        o0 = fmaf(w_, e0, o0); o1 = fmaf(w_, e1, o1); o2 = fmaf(w_, e2, o2);
    }
    {
        float ql = q1 * L2E, nm = -ql * qm;
        float e0 = ex2f_(fmaf(ql, q0, nm)), e1 = ex2f_(fmaf(ql, q1, nm)), e2 = ex2f_(fmaf(ql, q2, nm));
        float w_ = v1 / (e0 + e1 + e2);
        o0 = fmaf(w_, e0, o0); o1 = fmaf(w_, e1, o1); o2 = fmaf(w_, e2, o2);
    }
    {
        float ql = q2 * L2E, nm = -ql * qm;
        float e0 = ex2f_(fmaf(ql, q0, nm)), e1 = ex2f_(fmaf(ql, q1, nm)), e2 = ex2f_(fmaf(ql, q2, nm));
        float w_ = v2 / (e0 + e1 + e2);
        o0 = fmaf(w_, e0, o0); o1 = fmaf(w_, e1, o1); o2 = fmaf(w_, e2, o2);
    }

    float dat[3] = {o0, o1, o2};
    float qd[3]  = {q0, q1, q2};
    #pragma unroll
    for (int d = 0; d < 3; d++) {
        int s = c * 3 + d;
        int idx = base + d * HW;
        float patt;
        if (qd[d] > 0.f) {
            int b = (s << 12) + d_rank[idx];
            float p0 = 0.f;
            #pragma unroll
            for (int cc = 0; cc < 16; cc++) p0 += d_ppart[cc * NELEM + b];
            patt = p0;
        } else {
            float p0 = 0.f;
            #pragma unroll
            for (int cc = 0; cc < 16; cc++) p0 += d_AnzP[s][cc];
            patt = p0;
        }
        patt += d_S0[s];
        out[idx] = fmaf(gm, patt + dat[d], x[idx]);
    }
}

// ---------------------------------------------------------------------------
extern "C" void kernel_launch(void* const* d_in, const int* in_sizes, int n_in,
                              void* d_out, int out_size)
{
    const float* x    = (const float*)d_in[0];
    const float* W3   = (const float*)d_in[1];
    const float* b3   = (const float*)d_in[2];
    const float* g3   = (const float*)d_in[3];
    const float* be3  = (const float*)d_in[4];
    const float* W1   = (const float*)d_in[5];
    const float* b1   = (const float*)d_in[6];
    const float* g1   = (const float*)d_in[7];
    const float* be1  = (const float*)d_in[8];
    const float* gama = (const float*)d_in[9];
    float* out = (float*)d_out;

    k_pad  <<<341,  256>>>(x);
    k_conv <<<192,  256>>>(x, W3, b3, W1, b1);
    k_prep <<<12,  1024>>>(g3, be3, g1, be1);
    k_pass1<<<1536, 256>>>();
    k_pass2<<<3072, 256>>>();
    k_final<<<64,   256>>>(x, gama, out);
}